// round 2
// baseline (speedup 1.0000x reference)
#include <cuda_runtime.h>

// HDCHead: scores = sign(x @ proj) @ class_hv ; outputs (scores, hv_bin) concatenated.
// Round 1: full-fp32 SIMT baseline (calibration for rel_err before tensor-core rounds).

static constexpr int M1 = 16384;   // batch
static constexpr int K1 = 2048;    // IN_DIM
static constexpr int N1 = 8192;    // HV_DIM
static constexpr int N2 = 1000;    // NUM_CLASSES
static constexpr long long SCORES_ELEMS = (long long)M1 * N2;

#define TM 128
#define TN 128
#define TKK 16

// Tiled fp32 GEMM: C[M,N] = A[M,K] @ B[K,N]
// SIGN:   epilogue writes sign(acc) in {+1,-1}
// NGUARD: N not multiple of TN -> guarded B loads / C stores
template<bool SIGN, bool NGUARD>
__global__ __launch_bounds__(256)
void gemm_tiled(const float* __restrict__ A, const float* __restrict__ Bm,
                float* __restrict__ C, int M, int N, int K)
{
    __shared__ float As[TKK][TM];   // transposed A tile: As[k][m]
    __shared__ float Bs[TKK][TN];

    const int tid = threadIdx.x;
    const int m0 = blockIdx.y * TM;
    const int n0 = blockIdx.x * TN;
    const int tr = tid >> 4;   // 0..15  (thread row group)
    const int tc = tid & 15;   // 0..15  (thread col group)

    float acc[8][8];
#pragma unroll
    for (int i = 0; i < 8; ++i)
#pragma unroll
        for (int j = 0; j < 8; ++j) acc[i][j] = 0.f;

    for (int k0 = 0; k0 < K; k0 += TKK) {
        // --- load A tile (TM x TKK), store transposed ---
#pragma unroll
        for (int it = 0; it < 2; ++it) {
            int linear = it * 256 + tid;           // 0..511  (512 float4)
            int row = linear >> 2;                 // 0..127
            int c4  = (linear & 3) << 2;           // 0,4,8,12
            float4 v = *reinterpret_cast<const float4*>(
                &A[(long long)(m0 + row) * K + k0 + c4]);
            As[c4 + 0][row] = v.x;
            As[c4 + 1][row] = v.y;
            As[c4 + 2][row] = v.z;
            As[c4 + 3][row] = v.w;
        }
        // --- load B tile (TKK x TN) ---
        if (!NGUARD) {
#pragma unroll
            for (int it = 0; it < 2; ++it) {
                int linear = it * 256 + tid;       // 0..511
                int kr = linear >> 5;              // 0..15
                int c4 = (linear & 31) << 2;       // 0..124
                *reinterpret_cast<float4*>(&Bs[kr][c4]) =
                    *reinterpret_cast<const float4*>(
                        &Bm[(long long)(k0 + kr) * N + n0 + c4]);
            }
        } else {
#pragma unroll
            for (int it = 0; it < 8; ++it) {
                int linear = it * 256 + tid;       // 0..2047
                int kr = linear >> 7;              // 0..15
                int c  = linear & 127;
                int n  = n0 + c;
                Bs[kr][c] = (n < N) ? Bm[(long long)(k0 + kr) * N + n] : 0.f;
            }
        }
        __syncthreads();

        // --- compute 8x8 micro-tile ---
#pragma unroll
        for (int kk = 0; kk < TKK; ++kk) {
            float ra[8], rb[8];
            float4 a0 = *reinterpret_cast<const float4*>(&As[kk][tr * 8]);
            float4 a1 = *reinterpret_cast<const float4*>(&As[kk][tr * 8 + 4]);
            float4 b0 = *reinterpret_cast<const float4*>(&Bs[kk][tc * 8]);
            float4 b1 = *reinterpret_cast<const float4*>(&Bs[kk][tc * 8 + 4]);
            ra[0]=a0.x; ra[1]=a0.y; ra[2]=a0.z; ra[3]=a0.w;
            ra[4]=a1.x; ra[5]=a1.y; ra[6]=a1.z; ra[7]=a1.w;
            rb[0]=b0.x; rb[1]=b0.y; rb[2]=b0.z; rb[3]=b0.w;
            rb[4]=b1.x; rb[5]=b1.y; rb[6]=b1.z; rb[7]=b1.w;
#pragma unroll
            for (int i = 0; i < 8; ++i)
#pragma unroll
                for (int j = 0; j < 8; ++j)
                    acc[i][j] += ra[i] * rb[j];
        }
        __syncthreads();
    }

    // --- epilogue ---
#pragma unroll
    for (int i = 0; i < 8; ++i) {
        long long row = m0 + tr * 8 + i;
        if (!NGUARD) {
            float4 o0, o1;
            if (SIGN) {
                o0.x = acc[i][0] >= 0.f ? 1.f : -1.f;
                o0.y = acc[i][1] >= 0.f ? 1.f : -1.f;
                o0.z = acc[i][2] >= 0.f ? 1.f : -1.f;
                o0.w = acc[i][3] >= 0.f ? 1.f : -1.f;
                o1.x = acc[i][4] >= 0.f ? 1.f : -1.f;
                o1.y = acc[i][5] >= 0.f ? 1.f : -1.f;
                o1.z = acc[i][6] >= 0.f ? 1.f : -1.f;
                o1.w = acc[i][7] >= 0.f ? 1.f : -1.f;
            } else {
                o0.x = acc[i][0]; o0.y = acc[i][1]; o0.z = acc[i][2]; o0.w = acc[i][3];
                o1.x = acc[i][4]; o1.y = acc[i][5]; o1.z = acc[i][6]; o1.w = acc[i][7];
            }
            *reinterpret_cast<float4*>(&C[row * N + n0 + tc * 8])     = o0;
            *reinterpret_cast<float4*>(&C[row * N + n0 + tc * 8 + 4]) = o1;
        } else {
#pragma unroll
            for (int j = 0; j < 8; ++j) {
                int n = n0 + tc * 8 + j;
                if (n < N) {
                    float v = acc[i][j];
                    if (SIGN) v = v >= 0.f ? 1.f : -1.f;
                    C[row * N + n] = v;
                }
            }
        }
    }
}

extern "C" void kernel_launch(void* const* d_in, const int* in_sizes, int n_in,
                              void* d_out, int out_size)
{
    const float* x    = (const float*)d_in[0];   // [16384, 2048]
    const float* proj = (const float*)d_in[1];   // [2048, 8192]
    const float* chv  = (const float*)d_in[2];   // [8192, 1000]
    float* out    = (float*)d_out;
    float* scores = out;                          // [16384, 1000]
    float* hvbin  = out + SCORES_ELEMS;           // [16384, 8192]

    // GEMM1 fused sign: hv_bin = sign(x @ proj)
    dim3 g1(N1 / TN, M1 / TM);                    // (64, 128)
    gemm_tiled<true, false><<<g1, 256>>>(x, proj, hvbin, M1, N1, K1);

    // GEMM2: scores = hv_bin @ class_hv  (exact in fp32: +-1 sums)
    dim3 g2((N2 + TN - 1) / TN, M1 / TM);         // (8, 128)
    gemm_tiled<false, true><<<g2, 256>>>(hvbin, chv, scores, M1, N2, N1);
}

// round 5
// speedup vs baseline: 3.8930x; 3.8930x over previous
#include <cuda_runtime.h>
#include <cuda_bf16.h>
#include <cstdint>

// HDCHead: scores = sign(x@proj) @ class_hv ; outputs (scores[16384,1000], hv_bin[16384,8192]) f32.
// R4: HMMA bf16. GEMM1 split into TWO single-operand passes (hi, then lo+combine+sign),
// plus an exact-fp32 fixup pass for |hv| < TAU. GEMM2 bit-exact in bf16.

static constexpr int M1 = 16384, K1 = 2048, N1 = 8192, NC = 1000, NCP = 1024;
static constexpr long long SCORES_ELEMS = (long long)M1 * NC;
static constexpr float TAU = 0.05f;
static constexpr uint32_t FIXCAP = 1u << 22;

// -------- scratch (device globals: allocation-free rule) --------
__device__ __align__(256) __nv_bfloat16 g_xhi[(size_t)M1 * K1];     //  67MB
__device__ __align__(256) __nv_bfloat16 g_xlo[(size_t)M1 * K1];     //  67MB
__device__ __align__(256) __nv_bfloat16 g_projT[(size_t)N1 * K1];   //  33MB  [N1][K1]
__device__ __align__(256) __nv_bfloat16 g_chvT[(size_t)NCP * N1];   //  17MB  [1024][8192]
__device__ __align__(256) __nv_bfloat16 g_hvb[(size_t)M1 * N1];     // 268MB  bf16 sign
__device__ __align__(256) float         g_hvraw[(size_t)M1 * N1];   // 537MB  hv_hi fp32
__device__ uint32_t g_fixcnt;
__device__ uint32_t g_fixq[FIXCAP];                                 //  16MB

// -------- PTX helpers --------
__device__ __forceinline__ uint32_t smem_u32(const void* p) {
    uint32_t a;
    asm("{ .reg .u64 t; cvta.to.shared.u64 t, %1; cvt.u32.u64 %0, t; }" : "=r"(a) : "l"(p));
    return a;
}
__device__ __forceinline__ void cp16(uint32_t d, const void* s) {
    asm volatile("cp.async.cg.shared.global [%0], [%1], 16;" :: "r"(d), "l"(s));
}
#define CP_COMMIT() asm volatile("cp.async.commit_group;" ::: "memory")
#define CP_WAIT(n)  asm volatile("cp.async.wait_group %0;" :: "n"(n) : "memory")
#define SWZ(o) ((o) ^ (((o) >> 3) & 0x70))

__device__ __forceinline__ void ldsm4(uint32_t& r0, uint32_t& r1, uint32_t& r2, uint32_t& r3,
                                      uint32_t addr) {
    asm volatile("ldmatrix.sync.aligned.m8n8.x4.shared.b16 {%0,%1,%2,%3}, [%4];"
                 : "=r"(r0), "=r"(r1), "=r"(r2), "=r"(r3) : "r"(addr));
}
__device__ __forceinline__ void mma16816(float* d, const uint32_t* a, const uint32_t* b) {
    asm volatile("mma.sync.aligned.m16n8k16.row.col.f32.bf16.bf16.f32 "
                 "{%0,%1,%2,%3}, {%4,%5,%6,%7}, {%8,%9}, {%0,%1,%2,%3};"
                 : "+f"(d[0]), "+f"(d[1]), "+f"(d[2]), "+f"(d[3])
                 : "r"(a[0]), "r"(a[1]), "r"(a[2]), "r"(a[3]), "r"(b[0]), "r"(b[1]));
}

// -------- prep kernels --------
__global__ __launch_bounds__(256) void k_convert_x(const float4* __restrict__ x4) {
    size_t i = (size_t)blockIdx.x * 256 + threadIdx.x;
    float4 v = x4[i];
    __nv_bfloat16 h0 = __float2bfloat16(v.x), h1 = __float2bfloat16(v.y);
    __nv_bfloat16 h2 = __float2bfloat16(v.z), h3 = __float2bfloat16(v.w);
    __nv_bfloat16 l0 = __float2bfloat16(v.x - __bfloat162float(h0));
    __nv_bfloat16 l1 = __float2bfloat16(v.y - __bfloat162float(h1));
    __nv_bfloat16 l2 = __float2bfloat16(v.z - __bfloat162float(h2));
    __nv_bfloat16 l3 = __float2bfloat16(v.w - __bfloat162float(h3));
    __nv_bfloat162* ph = reinterpret_cast<__nv_bfloat162*>(g_xhi);
    __nv_bfloat162* pl = reinterpret_cast<__nv_bfloat162*>(g_xlo);
    ph[i * 2 + 0] = __nv_bfloat162(h0, h1);
    ph[i * 2 + 1] = __nv_bfloat162(h2, h3);
    pl[i * 2 + 0] = __nv_bfloat162(l0, l1);
    pl[i * 2 + 1] = __nv_bfloat162(l2, l3);
}

template<int WHICH>
__global__ __launch_bounds__(256) void k_transpose(const float* __restrict__ src, int R, int Csrc) {
    __nv_bfloat16* dst = (WHICH == 0) ? g_projT : g_chvT;
    __shared__ float t[32][33];
    int c0 = blockIdx.x * 32, r0 = blockIdx.y * 32;
    int tx = threadIdx.x & 31, ty = threadIdx.x >> 5;
#pragma unroll
    for (int j = 0; j < 4; ++j) {
        int r = r0 + ty + j * 8, c = c0 + tx;
        t[ty + j * 8][tx] = (c < Csrc) ? src[(size_t)r * Csrc + c] : 0.f;
    }
    __syncthreads();
#pragma unroll
    for (int j = 0; j < 4; ++j) {
        int c = c0 + ty + j * 8;
        dst[(size_t)c * R + r0 + tx] = __float2bfloat16(t[tx][ty + j * 8]);
    }
}

__global__ void k_zero() { g_fixcnt = 0; }

// -------- HMMA GEMM: 128x128 CTA tile, K-chunks of 64 bf16, 3-stage cp.async, PARTS=1 --------
// MODE 0: hv_hi = x_hi @ projT^T            -> g_hvraw (f32)
// MODE 1: hv = x_lo @ projT^T + g_hvraw     -> sign to outF(f32) + g_hvb(bf16), |hv|<TAU -> queue
// MODE 2: scores = g_hvb @ chvT^T           -> guarded f32 store (cols < 1000)
template<int MODE>
__global__ __launch_bounds__(256, 1) void hd_gemm(float* __restrict__ outF) {
    constexpr int  KTOT = (MODE < 2) ? K1 : N1;
    constexpr int  A_BYTES = 128 * 128;               // 128 rows x 64 bf16 (SW128)
    constexpr int  STAGE_BYTES = 2 * A_BYTES;
    constexpr int  STAGES = 3;
    constexpr int  C = KTOT / 64;

    extern __shared__ char smem[];
    const int tid = threadIdx.x;
    const int wid = tid >> 5, lane = tid & 31;
    const int wm = wid & 1;
    const int wn = wid >> 1;
    const int m0 = blockIdx.y * 128;
    const int n0 = blockIdx.x * 128;
    const uint32_t sb = smem_u32(smem);

    const __nv_bfloat16* __restrict__ Am =
        (MODE == 0) ? g_xhi : (MODE == 1) ? g_xlo : g_hvb;
    const __nv_bfloat16* __restrict__ Bt = (MODE < 2) ? g_projT : g_chvT;

    float acc[4][4][4];
#pragma unroll
    for (int i = 0; i < 4; ++i)
#pragma unroll
        for (int j = 0; j < 4; ++j)
#pragma unroll
            for (int q = 0; q < 4; ++q) acc[i][j][q] = 0.f;

    auto load_stage = [&](int chunk, int st) {
        uint32_t base = sb + st * STAGE_BYTES;
#pragma unroll
        for (int i = 0; i < 4; ++i) {
            int u = tid + i * 256, r = u >> 3, cc = u & 7;
            cp16(base + SWZ(r * 128 + cc * 16),
                 Am + (size_t)(m0 + r) * KTOT + chunk * 64 + cc * 8);
        }
#pragma unroll
        for (int i = 0; i < 4; ++i) {
            int u = tid + i * 256, r = u >> 3, cc = u & 7;
            cp16(base + A_BYTES + SWZ(r * 128 + cc * 16),
                 Bt + (size_t)(n0 + r) * KTOT + chunk * 64 + cc * 8);
        }
    };

    for (int p = 0; p < STAGES - 1; ++p) { load_stage(p, p); CP_COMMIT(); }

    const int a_row = lane & 15;
    const int a_cb  = (lane >> 4) << 4;
    const int b_row = ((lane >> 4) << 3) + (lane & 7);
    const int b_cb  = ((lane >> 3) & 1) << 4;

    for (int c = 0; c < C; ++c) {
        int st = c % STAGES;
        if (c < C - 1) { CP_WAIT(1); } else { CP_WAIT(0); }
        __syncthreads();
        int nxt = c + STAGES - 1;
        if (nxt < C) { load_stage(nxt, nxt % STAGES); CP_COMMIT(); }

        uint32_t aBase = sb + st * STAGE_BYTES;
        uint32_t bBase = aBase + A_BYTES;
#pragma unroll
        for (int ks = 0; ks < 4; ++ks) {
            int kb = ks * 32;
            uint32_t bfr[2][4];
#pragma unroll
            for (int j2 = 0; j2 < 2; ++j2) {
                int nrow = wn * 32 + j2 * 16 + b_row;
                ldsm4(bfr[j2][0], bfr[j2][1], bfr[j2][2], bfr[j2][3],
                      bBase + SWZ(nrow * 128 + kb + b_cb));
            }
#pragma unroll
            for (int i = 0; i < 4; ++i) {
                int mrow = wm * 64 + i * 16 + a_row;
                uint32_t afr[4];
                ldsm4(afr[0], afr[1], afr[2], afr[3],
                      aBase + SWZ(mrow * 128 + kb + a_cb));
#pragma unroll
                for (int j = 0; j < 4; ++j)
                    mma16816(acc[i][j], afr, &bfr[j >> 1][(j & 1) * 2]);
            }
        }
        __syncthreads();
    }

    // -------- epilogue --------
    const int gid = lane >> 2, tid4 = lane & 3;
#pragma unroll
    for (int i = 0; i < 4; ++i) {
#pragma unroll
        for (int half = 0; half < 2; ++half) {
            size_t row = m0 + wm * 64 + i * 16 + gid + half * 8;
#pragma unroll
            for (int j = 0; j < 4; ++j) {
                int col = n0 + wn * 32 + j * 8 + tid4 * 2;
                float v0 = acc[i][j][half * 2 + 0];
                float v1 = acc[i][j][half * 2 + 1];
                if (MODE == 0) {
                    *reinterpret_cast<float2*>(g_hvraw + row * (size_t)N1 + col) =
                        make_float2(v0, v1);
                } else if (MODE == 1) {
                    float2 prev = *reinterpret_cast<const float2*>(
                        g_hvraw + row * (size_t)N1 + col);
                    v0 += prev.x; v1 += prev.y;
                    float s0 = (v0 >= 0.f) ? 1.f : -1.f;
                    float s1 = (v1 >= 0.f) ? 1.f : -1.f;
                    *reinterpret_cast<float2*>(outF + row * (size_t)N1 + col) =
                        make_float2(s0, s1);
                    __nv_bfloat162 t2(__float2bfloat16(s0), __float2bfloat16(s1));
                    *reinterpret_cast<__nv_bfloat162*>(g_hvb + row * (size_t)N1 + col) = t2;
                    if (fabsf(v0) < TAU) {
                        uint32_t idx = atomicAdd(&g_fixcnt, 1u);
                        if (idx < FIXCAP) g_fixq[idx] = ((uint32_t)row << 13) | (uint32_t)col;
                    }
                    if (fabsf(v1) < TAU) {
                        uint32_t idx = atomicAdd(&g_fixcnt, 1u);
                        if (idx < FIXCAP) g_fixq[idx] = ((uint32_t)row << 13) | (uint32_t)(col + 1);
                    }
                } else {
                    if (col < NC)
                        *reinterpret_cast<float2*>(outF + row * (size_t)NC + col) =
                            make_float2(v0, v1);
                }
            }
        }
    }
}

// -------- exact fixup: warp per queued element, Kahan fp32 dot over K1 --------
__global__ __launch_bounds__(128) void k_fixup(const float* __restrict__ x,
                                               float* __restrict__ hvf32) {
    uint32_t total = g_fixcnt;
    if (total > FIXCAP) total = FIXCAP;
    int gw = (blockIdx.x * 128 + threadIdx.x) >> 5;
    int lane = threadIdx.x & 31;
    int nw = (gridDim.x * 128) >> 5;
    for (uint32_t w = gw; w < total; w += nw) {
        uint32_t e = g_fixq[w];
        uint32_t row = e >> 13, col = e & 8191u;
        const float* xr = x + (size_t)row * K1;
        const __nv_bfloat16* pr = g_projT + (size_t)col * K1;
        float s = 0.f, comp = 0.f;
#pragma unroll 4
        for (int j = 0; j < K1 / 32; ++j) {
            int k = lane + j * 32;
            float t = xr[k] * __bfloat162float(pr[k]);
            float y = t - comp;
            float u = s + y;
            comp = (u - s) - y;
            s = u;
        }
#pragma unroll
        for (int o = 16; o > 0; o >>= 1) s += __shfl_xor_sync(0xFFFFFFFFu, s, o);
        if (lane == 0) {
            float sg = (s >= 0.f) ? 1.f : -1.f;
            hvf32[(size_t)row * N1 + col] = sg;
            g_hvb[(size_t)row * N1 + col] = __float2bfloat16(sg);
        }
    }
}

// -------- launch --------
extern "C" void kernel_launch(void* const* d_in, const int* in_sizes, int n_in,
                              void* d_out, int out_size)
{
    const float* x    = (const float*)d_in[0];
    const float* proj = (const float*)d_in[1];
    const float* chv  = (const float*)d_in[2];
    float* scores = (float*)d_out;
    float* hvf32  = (float*)d_out + SCORES_ELEMS;

    constexpr int SMB = 3 * 2 * 128 * 128;   // 98304
    cudaFuncSetAttribute(hd_gemm<0>, cudaFuncAttributeMaxDynamicSharedMemorySize, SMB);
    cudaFuncSetAttribute(hd_gemm<1>, cudaFuncAttributeMaxDynamicSharedMemorySize, SMB);
    cudaFuncSetAttribute(hd_gemm<2>, cudaFuncAttributeMaxDynamicSharedMemorySize, SMB);

    k_convert_x<<<32768, 256>>>((const float4*)x);
    k_transpose<0><<<dim3(N1 / 32, K1 / 32), 256>>>(proj, K1, N1);
    k_transpose<1><<<dim3(NCP / 32, N1 / 32), 256>>>(chv, N1, NC);

    hd_gemm<0><<<dim3(N1 / 128, M1 / 128), 256, SMB>>>(nullptr);   // hi -> g_hvraw
    k_zero<<<1, 1>>>();
    hd_gemm<1><<<dim3(N1 / 128, M1 / 128), 256, SMB>>>(hvf32);     // lo + combine + sign
    k_fixup<<<2048, 128>>>(x, hvf32);
    hd_gemm<2><<<dim3(NCP / 128, M1 / 128), 256, SMB>>>(scores);   // scores
}

// round 6
// speedup vs baseline: 5.0097x; 1.2868x over previous
#include <cuda_runtime.h>
#include <cuda_bf16.h>
#include <cstdint>

// HDCHead: scores = sign(x@proj) @ class_hv ; outputs (scores[16384,1000], hv_bin[16384,8192]) f32.
// R5: fused 2-term bf16-split GEMM1 (single pass, hi+lo share B fragments) + exact fp32 fixup
// for |hv| < TAU + bit-exact bf16 GEMM2.

static constexpr int M1 = 16384, K1 = 2048, N1 = 8192, NC = 1000, NCP = 1024;
static constexpr long long SCORES_ELEMS = (long long)M1 * NC;
static constexpr float TAU = 0.05f;
static constexpr uint32_t FIXCAP = 1u << 22;

// -------- scratch (device globals: allocation-free rule) --------
__device__ __align__(256) __nv_bfloat16 g_xhi[(size_t)M1 * K1];     //  67MB
__device__ __align__(256) __nv_bfloat16 g_xlo[(size_t)M1 * K1];     //  67MB
__device__ __align__(256) __nv_bfloat16 g_projT[(size_t)N1 * K1];   //  33MB  [N1][K1]
__device__ __align__(256) __nv_bfloat16 g_chvT[(size_t)NCP * N1];   //  17MB  [1024][8192]
__device__ __align__(256) __nv_bfloat16 g_hvb[(size_t)M1 * N1];     // 268MB  bf16 sign
__device__ uint32_t g_fixcnt;
__device__ uint32_t g_fixq[FIXCAP];                                 //  16MB

// -------- PTX helpers --------
__device__ __forceinline__ uint32_t smem_u32(const void* p) {
    uint32_t a;
    asm("{ .reg .u64 t; cvta.to.shared.u64 t, %1; cvt.u32.u64 %0, t; }" : "=r"(a) : "l"(p));
    return a;
}
__device__ __forceinline__ void cp16(uint32_t d, const void* s) {
    asm volatile("cp.async.cg.shared.global [%0], [%1], 16;" :: "r"(d), "l"(s));
}
#define CP_COMMIT() asm volatile("cp.async.commit_group;" ::: "memory")
#define CP_WAIT(n)  asm volatile("cp.async.wait_group %0;" :: "n"(n) : "memory")
#define SWZ(o) ((o) ^ (((o) >> 3) & 0x70))

__device__ __forceinline__ void ldsm4(uint32_t& r0, uint32_t& r1, uint32_t& r2, uint32_t& r3,
                                      uint32_t addr) {
    asm volatile("ldmatrix.sync.aligned.m8n8.x4.shared.b16 {%0,%1,%2,%3}, [%4];"
                 : "=r"(r0), "=r"(r1), "=r"(r2), "=r"(r3) : "r"(addr));
}
__device__ __forceinline__ void mma16816(float* d, const uint32_t* a, const uint32_t* b) {
    asm volatile("mma.sync.aligned.m16n8k16.row.col.f32.bf16.bf16.f32 "
                 "{%0,%1,%2,%3}, {%4,%5,%6,%7}, {%8,%9}, {%0,%1,%2,%3};"
                 : "+f"(d[0]), "+f"(d[1]), "+f"(d[2]), "+f"(d[3])
                 : "r"(a[0]), "r"(a[1]), "r"(a[2]), "r"(a[3]), "r"(b[0]), "r"(b[1]));
}

// -------- prep kernels --------
__global__ __launch_bounds__(256) void k_convert_x(const float4* __restrict__ x4) {
    size_t i = (size_t)blockIdx.x * 256 + threadIdx.x;
    float4 v = x4[i];
    __nv_bfloat16 h0 = __float2bfloat16(v.x), h1 = __float2bfloat16(v.y);
    __nv_bfloat16 h2 = __float2bfloat16(v.z), h3 = __float2bfloat16(v.w);
    __nv_bfloat16 l0 = __float2bfloat16(v.x - __bfloat162float(h0));
    __nv_bfloat16 l1 = __float2bfloat16(v.y - __bfloat162float(h1));
    __nv_bfloat16 l2 = __float2bfloat16(v.z - __bfloat162float(h2));
    __nv_bfloat16 l3 = __float2bfloat16(v.w - __bfloat162float(h3));
    __nv_bfloat162* ph = reinterpret_cast<__nv_bfloat162*>(g_xhi);
    __nv_bfloat162* pl = reinterpret_cast<__nv_bfloat162*>(g_xlo);
    ph[i * 2 + 0] = __nv_bfloat162(h0, h1);
    ph[i * 2 + 1] = __nv_bfloat162(h2, h3);
    pl[i * 2 + 0] = __nv_bfloat162(l0, l1);
    pl[i * 2 + 1] = __nv_bfloat162(l2, l3);
}

template<int WHICH>
__global__ __launch_bounds__(256) void k_transpose(const float* __restrict__ src, int R, int Csrc) {
    __nv_bfloat16* dst = (WHICH == 0) ? g_projT : g_chvT;
    __shared__ float t[32][33];
    int c0 = blockIdx.x * 32, r0 = blockIdx.y * 32;
    int tx = threadIdx.x & 31, ty = threadIdx.x >> 5;
#pragma unroll
    for (int j = 0; j < 4; ++j) {
        int r = r0 + ty + j * 8, c = c0 + tx;
        t[ty + j * 8][tx] = (c < Csrc) ? src[(size_t)r * Csrc + c] : 0.f;
    }
    __syncthreads();
#pragma unroll
    for (int j = 0; j < 4; ++j) {
        int c = c0 + ty + j * 8;
        dst[(size_t)c * R + r0 + tx] = __float2bfloat16(t[tx][ty + j * 8]);
    }
}

__global__ void k_zero() { g_fixcnt = 0; }

// -------- HMMA GEMM: 128x128 CTA tile, K-chunks of 64 bf16, 3-stage cp.async --------
// MODE 1: hv = (x_hi + x_lo) @ projT^T (fused split) -> sign to outF + g_hvb, |hv|<TAU -> queue
// MODE 2: scores = g_hvb @ chvT^T -> guarded f32 store (cols < 1000)
template<int MODE>
__global__ __launch_bounds__(256, 1) void hd_gemm(float* __restrict__ outF) {
    constexpr bool SPLIT = (MODE == 1);
    constexpr int  KTOT = SPLIT ? K1 : N1;
    constexpr int  PARTS = SPLIT ? 2 : 1;
    constexpr int  A_BYTES = 128 * 128;               // 128 rows x 64 bf16 (SW128)
    constexpr int  B_OFF   = A_BYTES * PARTS;
    constexpr int  STAGE_BYTES = B_OFF + A_BYTES;
    constexpr int  STAGES = 3;
    constexpr int  C = KTOT / 64;

    extern __shared__ char smem[];
    const int tid = threadIdx.x;
    const int wid = tid >> 5, lane = tid & 31;
    const int wm = wid & 1;
    const int wn = wid >> 1;
    const int m0 = blockIdx.y * 128;
    const int n0 = blockIdx.x * 128;
    const uint32_t sb = smem_u32(smem);

    const __nv_bfloat16* __restrict__ Ahi = SPLIT ? g_xhi : g_hvb;
    const __nv_bfloat16* __restrict__ Alo = g_xlo;
    const __nv_bfloat16* __restrict__ Bt  = SPLIT ? g_projT : g_chvT;

    float acc[4][4][4];
#pragma unroll
    for (int i = 0; i < 4; ++i)
#pragma unroll
        for (int j = 0; j < 4; ++j)
#pragma unroll
            for (int q = 0; q < 4; ++q) acc[i][j][q] = 0.f;

    auto load_stage = [&](int chunk, int st) {
        uint32_t base = sb + st * STAGE_BYTES;
#pragma unroll
        for (int p = 0; p < PARTS; ++p) {
            const __nv_bfloat16* src = (p == 0) ? Ahi : Alo;
#pragma unroll
            for (int i = 0; i < 4; ++i) {
                int u = tid + i * 256, r = u >> 3, cc = u & 7;
                cp16(base + p * A_BYTES + SWZ(r * 128 + cc * 16),
                     src + (size_t)(m0 + r) * KTOT + chunk * 64 + cc * 8);
            }
        }
#pragma unroll
        for (int i = 0; i < 4; ++i) {
            int u = tid + i * 256, r = u >> 3, cc = u & 7;
            cp16(base + B_OFF + SWZ(r * 128 + cc * 16),
                 Bt + (size_t)(n0 + r) * KTOT + chunk * 64 + cc * 8);
        }
    };

    for (int p = 0; p < STAGES - 1; ++p) { load_stage(p, p); CP_COMMIT(); }

    const int a_row = lane & 15;
    const int a_cb  = (lane >> 4) << 4;
    const int b_row = ((lane >> 4) << 3) + (lane & 7);
    const int b_cb  = ((lane >> 3) & 1) << 4;

    for (int c = 0; c < C; ++c) {
        int st = c % STAGES;
        if (c < C - 1) { CP_WAIT(1); } else { CP_WAIT(0); }
        __syncthreads();
        int nxt = c + STAGES - 1;
        if (nxt < C) { load_stage(nxt, nxt % STAGES); CP_COMMIT(); }

        uint32_t aBase = sb + st * STAGE_BYTES;
        uint32_t bBase = aBase + B_OFF;
#pragma unroll
        for (int ks = 0; ks < 4; ++ks) {
            int kb = ks * 32;
            uint32_t bfr[2][4];
#pragma unroll
            for (int j2 = 0; j2 < 2; ++j2) {
                int nrow = wn * 32 + j2 * 16 + b_row;
                ldsm4(bfr[j2][0], bfr[j2][1], bfr[j2][2], bfr[j2][3],
                      bBase + SWZ(nrow * 128 + kb + b_cb));
            }
#pragma unroll
            for (int part = 0; part < PARTS; ++part) {
                uint32_t aP = aBase + part * A_BYTES;
#pragma unroll
                for (int i = 0; i < 4; ++i) {
                    int mrow = wm * 64 + i * 16 + a_row;
                    uint32_t afr[4];
                    ldsm4(afr[0], afr[1], afr[2], afr[3],
                          aP + SWZ(mrow * 128 + kb + a_cb));
#pragma unroll
                    for (int j = 0; j < 4; ++j)
                        mma16816(acc[i][j], afr, &bfr[j >> 1][(j & 1) * 2]);
                }
            }
        }
        __syncthreads();
    }

    // -------- epilogue --------
    const int gid = lane >> 2, tid4 = lane & 3;
#pragma unroll
    for (int i = 0; i < 4; ++i) {
#pragma unroll
        for (int half = 0; half < 2; ++half) {
            size_t row = m0 + wm * 64 + i * 16 + gid + half * 8;
#pragma unroll
            for (int j = 0; j < 4; ++j) {
                int col = n0 + wn * 32 + j * 8 + tid4 * 2;
                float v0 = acc[i][j][half * 2 + 0];
                float v1 = acc[i][j][half * 2 + 1];
                if (MODE == 1) {
                    float s0 = (v0 >= 0.f) ? 1.f : -1.f;
                    float s1 = (v1 >= 0.f) ? 1.f : -1.f;
                    *reinterpret_cast<float2*>(outF + row * (size_t)N1 + col) =
                        make_float2(s0, s1);
                    __nv_bfloat162 t2(__float2bfloat16(s0), __float2bfloat16(s1));
                    *reinterpret_cast<__nv_bfloat162*>(g_hvb + row * (size_t)N1 + col) = t2;
                    if (fabsf(v0) < TAU) {
                        uint32_t idx = atomicAdd(&g_fixcnt, 1u);
                        if (idx < FIXCAP) g_fixq[idx] = ((uint32_t)row << 13) | (uint32_t)col;
                    }
                    if (fabsf(v1) < TAU) {
                        uint32_t idx = atomicAdd(&g_fixcnt, 1u);
                        if (idx < FIXCAP) g_fixq[idx] = ((uint32_t)row << 13) | (uint32_t)(col + 1);
                    }
                } else {
                    if (col < NC)
                        *reinterpret_cast<float2*>(outF + row * (size_t)NC + col) =
                            make_float2(v0, v1);
                }
            }
        }
    }
}

// -------- exact fixup: warp per queued element, Kahan fp32 dot over K1 --------
__global__ __launch_bounds__(128) void k_fixup(const float* __restrict__ x,
                                               float* __restrict__ hvf32) {
    uint32_t total = g_fixcnt;
    if (total > FIXCAP) total = FIXCAP;
    int gw = (blockIdx.x * 128 + threadIdx.x) >> 5;
    int lane = threadIdx.x & 31;
    int nw = (gridDim.x * 128) >> 5;
    for (uint32_t w = gw; w < total; w += nw) {
        uint32_t e = g_fixq[w];
        uint32_t row = e >> 13, col = e & 8191u;
        const float* xr = x + (size_t)row * K1;
        const __nv_bfloat16* pr = g_projT + (size_t)col * K1;
        float s = 0.f, comp = 0.f;
#pragma unroll 4
        for (int j = 0; j < K1 / 32; ++j) {
            int k = lane + j * 32;
            float t = xr[k] * __bfloat162float(pr[k]);
            float y = t - comp;
            float u = s + y;
            comp = (u - s) - y;
            s = u;
        }
#pragma unroll
        for (int o = 16; o > 0; o >>= 1) s += __shfl_xor_sync(0xFFFFFFFFu, s, o);
        if (lane == 0) {
            float sg = (s >= 0.f) ? 1.f : -1.f;
            hvf32[(size_t)row * N1 + col] = sg;
            g_hvb[(size_t)row * N1 + col] = __float2bfloat16(sg);
        }
    }
}

// -------- launch --------
extern "C" void kernel_launch(void* const* d_in, const int* in_sizes, int n_in,
                              void* d_out, int out_size)
{
    const float* x    = (const float*)d_in[0];
    const float* proj = (const float*)d_in[1];
    const float* chv  = (const float*)d_in[2];
    float* scores = (float*)d_out;
    float* hvf32  = (float*)d_out + SCORES_ELEMS;

    constexpr int SM1 = 3 * 3 * 128 * 128;   // 147456 (Ahi+Alo+B per stage)
    constexpr int SM2 = 3 * 2 * 128 * 128;   // 98304
    cudaFuncSetAttribute(hd_gemm<1>, cudaFuncAttributeMaxDynamicSharedMemorySize, SM1);
    cudaFuncSetAttribute(hd_gemm<2>, cudaFuncAttributeMaxDynamicSharedMemorySize, SM2);

    k_convert_x<<<32768, 256>>>((const float4*)x);
    k_transpose<0><<<dim3(N1 / 32, K1 / 32), 256>>>(proj, K1, N1);
    k_transpose<1><<<dim3(NCP / 32, N1 / 32), 256>>>(chv, N1, NC);
    k_zero<<<1, 1>>>();

    hd_gemm<1><<<dim3(N1 / 128, M1 / 128), 256, SM1>>>(hvf32);   // fused hi+lo, sign, queue
    k_fixup<<<2048, 128>>>(x, hvf32);
    hd_gemm<2><<<dim3(NCP / 128, M1 / 128), 256, SM2>>>(scores); // scores
}